// round 1
// baseline (speedup 1.0000x reference)
#include <cuda_runtime.h>
#include <cuda_bf16.h>
#include <mma.h>

using namespace nvcuda;

#define BB 2048
#define NN 128
#define DD 512

// scratch: cw planes [k][b][d], k=0 text-row, k=1 img-row. 8 MB static.
__device__ float g_cw[2 * BB * DD];

__device__ __forceinline__ float tanh_ap(float x) {
    float y;
    asm("tanh.approx.f32 %0, %1;" : "=f"(y) : "f"(x));
    return y;
}

__device__ __forceinline__ void bsplit(float x, __nv_bfloat16& h, __nv_bfloat16& l) {
    __nv_bfloat16 hh = __float2bfloat16(x);
    h = hh;
    l = __float2bfloat16(x - __bfloat162float(hh));
}

// ---------------------------------------------------------------------------
// Kernel A: cw[k] = content_k @ cow  via bf16 hi/lo split (3 MMA products).
// Block tile 64(M) x 64(N), K-chunk 32, 128 threads (4 warps of 32x32 tiles).
// grid = (DD/64, BB/64, 2)
// ---------------------------------------------------------------------------
__global__ __launch_bounds__(128) void cw_gemm(
    const float* __restrict__ text, const float* __restrict__ img,
    const float* __restrict__ cow)
{
    const int plane = blockIdx.z;
    const float* __restrict__ A = plane ? img : text;
    float* __restrict__ C = g_cw + (size_t)plane * BB * DD;
    const int rowBase = blockIdx.y * 64;
    const int colBase = blockIdx.x * 64;
    const int tid = threadIdx.x;
    const int warp = tid >> 5;
    const int wm = warp >> 1, wn = warp & 1;

    __shared__ __nv_bfloat16 sAh[64][40], sAl[64][40];
    __shared__ __nv_bfloat16 sBh[32][72], sBl[32][72];

    wmma::fragment<wmma::accumulator, 16, 16, 16, float> acc[2][2];
#pragma unroll
    for (int i = 0; i < 2; i++)
#pragma unroll
        for (int j = 0; j < 2; j++) wmma::fill_fragment(acc[i][j], 0.0f);

    for (int kc = 0; kc < DD; kc += 32) {
#pragma unroll
        for (int it = 0; it < 4; it++) {
            int q = tid + it * 128;
            {   // A tile: 64 rows x 32 cols -> 512 float4
                int r = q >> 3, c4 = q & 7;
                float4 v = *(const float4*)(A + (size_t)(rowBase + r) * DD + kc + c4 * 4);
                bsplit(v.x, sAh[r][c4*4+0], sAl[r][c4*4+0]);
                bsplit(v.y, sAh[r][c4*4+1], sAl[r][c4*4+1]);
                bsplit(v.z, sAh[r][c4*4+2], sAl[r][c4*4+2]);
                bsplit(v.w, sAh[r][c4*4+3], sAl[r][c4*4+3]);
            }
            {   // B tile (cow): 32 rows x 64 cols -> 512 float4
                int r = q >> 4, c4 = q & 15;
                float4 v = *(const float4*)(cow + (size_t)(kc + r) * DD + colBase + c4 * 4);
                bsplit(v.x, sBh[r][c4*4+0], sBl[r][c4*4+0]);
                bsplit(v.y, sBh[r][c4*4+1], sBl[r][c4*4+1]);
                bsplit(v.z, sBh[r][c4*4+2], sBl[r][c4*4+2]);
                bsplit(v.w, sBh[r][c4*4+3], sBl[r][c4*4+3]);
            }
        }
        __syncthreads();
#pragma unroll
        for (int ks = 0; ks < 32; ks += 16) {
            wmma::fragment<wmma::matrix_a, 16, 16, 16, __nv_bfloat16, wmma::row_major> ah[2], al[2];
            wmma::fragment<wmma::matrix_b, 16, 16, 16, __nv_bfloat16, wmma::row_major> bh[2], bl[2];
#pragma unroll
            for (int i = 0; i < 2; i++) {
                wmma::load_matrix_sync(ah[i], &sAh[wm*32 + i*16][ks], 40);
                wmma::load_matrix_sync(al[i], &sAl[wm*32 + i*16][ks], 40);
                wmma::load_matrix_sync(bh[i], &sBh[ks][wn*32 + i*16], 72);
                wmma::load_matrix_sync(bl[i], &sBl[ks][wn*32 + i*16], 72);
            }
#pragma unroll
            for (int i = 0; i < 2; i++)
#pragma unroll
                for (int j = 0; j < 2; j++) {
                    wmma::mma_sync(acc[i][j], ah[i], bh[j], acc[i][j]);
                    wmma::mma_sync(acc[i][j], ah[i], bl[j], acc[i][j]);
                    wmma::mma_sync(acc[i][j], al[i], bh[j], acc[i][j]);
                }
        }
        __syncthreads();
    }
#pragma unroll
    for (int i = 0; i < 2; i++)
#pragma unroll
        for (int j = 0; j < 2; j++)
            wmma::store_matrix_sync(
                C + (size_t)(rowBase + wm*32 + i*16) * DD + colBase + wn*32 + j*16,
                acc[i][j], DD, wmma::mem_row_major);
}

// ---------------------------------------------------------------------------
// Kernel B: fused co-attention, one CTA per sample, 4 warps.
// Warp w handles comment rows n = w, w+4, ...  Single pass over comment.
// ---------------------------------------------------------------------------
__global__ __launch_bounds__(128, 3) void fused_coattn(
    const float* __restrict__ text, const float* __restrict__ img,
    const float* __restrict__ comment, const int* __restrict__ comment_num,
    const float* __restrict__ W_ca, const float* __restrict__ W_co,
    float* __restrict__ out)
{
    const int b = blockIdx.x;
    const int tid = threadIdx.x;
    const int lane = tid & 31;
    const int warp = tid >> 5;
    const int M = comment_num[b];

    __shared__ float s_c0[DD], s_c1[DD], s_Wca[DD], s_Wco[DD];
    __shared__ float s_red[4][3 * DD];
    __shared__ float s_mz[4][2];
    __shared__ float s_scalar[8];

    // cooperative loads of the small per-sample vectors
    for (int i = tid; i < DD / 4; i += 128) {
        ((float4*)s_c0)[i]  = ((const float4*)(text + (size_t)b * DD))[i];
        ((float4*)s_c1)[i]  = ((const float4*)(img  + (size_t)b * DD))[i];
        ((float4*)s_Wca)[i] = ((const float4*)W_ca)[i];
        ((float4*)s_Wco)[i] = ((const float4*)W_co)[i];
    }
    __syncthreads();

    // per-lane register vectors (element mapping: d = 4*(j*32+lane)+c)
    float cw0[16], cw1[16], c0r[16], c1r[16];
    {
        const float* cw0p = g_cw + (size_t)b * DD;
        const float* cw1p = g_cw + (size_t)BB * DD + (size_t)b * DD;
#pragma unroll
        for (int j = 0; j < 4; j++) {
            int f = j * 32 + lane;
            float4 t;
            t = *(const float4*)(cw0p + 4*f); cw0[4*j]=t.x; cw0[4*j+1]=t.y; cw0[4*j+2]=t.z; cw0[4*j+3]=t.w;
            t = *(const float4*)(cw1p + 4*f); cw1[4*j]=t.x; cw1[4*j+1]=t.y; cw1[4*j+2]=t.z; cw1[4*j+3]=t.w;
            t = *(const float4*)(s_c0 + 4*f); c0r[4*j]=t.x; c0r[4*j+1]=t.y; c0r[4*j+2]=t.z; c0r[4*j+3]=t.w;
            t = *(const float4*)(s_c1 + 4*f); c1r[4*j]=t.x; c1r[4*j+1]=t.y; c1r[4*j+2]=t.z; c1r[4*j+3]=t.w;
        }
    }

    float acc0[16], acc1[16], aa[16];
#pragma unroll
    for (int j = 0; j < 16; j++) { acc0[j] = 0.f; acc1[j] = 0.f; aa[j] = 0.f; }
    float mrun = -3.4e38f, Zrun = 0.f;

    // prefetch first row for this warp
    float znext[16];
    if (warp < M) {
        const float4* p = (const float4*)(comment + ((size_t)b * NN + warp) * DD);
#pragma unroll
        for (int j = 0; j < 4; j++) {
            float4 t = __ldcs(p + j * 32 + lane);
            znext[4*j]=t.x; znext[4*j+1]=t.y; znext[4*j+2]=t.z; znext[4*j+3]=t.w;
        }
    }

    for (int n = warp; n < M; n += 4) {
        float z[16];
#pragma unroll
        for (int j = 0; j < 16; j++) z[j] = znext[j];
        if (n + 4 < M) {
            const float4* p = (const float4*)(comment + ((size_t)b * NN + n + 4) * DD);
#pragma unroll
            for (int j = 0; j < 4; j++) {
                float4 t = __ldcs(p + j * 32 + lane);
                znext[4*j]=t.x; znext[4*j+1]=t.y; znext[4*j+2]=t.z; znext[4*j+3]=t.w;
            }
        }

        // s_k = cw_k . z  (warp dot)
        float s0 = 0.f, s1 = 0.f;
#pragma unroll
        for (int j = 0; j < 16; j++) { s0 = fmaf(cw0[j], z[j], s0); s1 = fmaf(cw1[j], z[j], s1); }
#pragma unroll
        for (int o = 16; o; o >>= 1) {
            s0 += __shfl_xor_sync(0xffffffffu, s0, o);
            s1 += __shfl_xor_sync(0xffffffffu, s1, o);
        }
        float w0 = tanh_ap(s0), w1 = tanh_ap(s1);

        // accumulate co_w*z; comment-attention logit
        float l = 0.f;
#pragma unroll
        for (int j = 0; j < 4; j++) {
            float4 wv = *(const float4*)(s_Wco + 4 * (j * 32 + lane));
            float wl[4] = {wv.x, wv.y, wv.z, wv.w};
#pragma unroll
            for (int c = 0; c < 4; c++) {
                int e = 4 * j + c;
                acc0[e] = fmaf(w0, z[e], acc0[e]);
                acc1[e] = fmaf(w1, z[e], acc1[e]);
                float v = fmaf(w0, c0r[e], fmaf(w1, c1r[e], z[e]));
                l = fmaf(tanh_ap(v), wl[c], l);
            }
        }
#pragma unroll
        for (int o = 16; o; o >>= 1) l += __shfl_xor_sync(0xffffffffu, l, o);

        // online softmax update (l is warp-uniform -> no divergence)
        if (l <= mrun) {
            float p = __expf(l - mrun);
            Zrun += p;
#pragma unroll
            for (int j = 0; j < 16; j++) aa[j] = fmaf(p, z[j], aa[j]);
        } else {
            float sc = __expf(mrun - l);
            Zrun = fmaf(Zrun, sc, 1.f);
#pragma unroll
            for (int j = 0; j < 16; j++) aa[j] = fmaf(aa[j], sc, z[j]);
            mrun = l;
        }
    }

    // spill per-warp partials to shared
#pragma unroll
    for (int j = 0; j < 4; j++) {
        int f = j * 32 + lane;
        *(float4*)(s_red[warp] + 4*f)          = make_float4(acc0[4*j], acc0[4*j+1], acc0[4*j+2], acc0[4*j+3]);
        *(float4*)(s_red[warp] + DD + 4*f)     = make_float4(acc1[4*j], acc1[4*j+1], acc1[4*j+2], acc1[4*j+3]);
        *(float4*)(s_red[warp] + 2*DD + 4*f)   = make_float4(aa[4*j],   aa[4*j+1],   aa[4*j+2],   aa[4*j+3]);
    }
    if (lane == 0) { s_mz[warp][0] = mrun; s_mz[warp][1] = Zrun; }
    __syncthreads();

    // combine across warps; thread t owns float4 index t (d = 4t..4t+3)
    float mg = s_mz[0][0];
#pragma unroll
    for (int w = 1; w < 4; w++) mg = fmaxf(mg, s_mz[w][0]);
    float Zg = 0.f, coef[4];
#pragma unroll
    for (int w = 0; w < 4; w++) {
        coef[w] = __expf(s_mz[w][0] - mg);
        Zg = fmaf(s_mz[w][1], coef[w], Zg);
    }
    float invZ = 1.f / Zg;

    float a0[4] = {0,0,0,0}, a1[4] = {0,0,0,0}, av[4] = {0,0,0,0};
#pragma unroll
    for (int w = 0; w < 4; w++) {
        float4 x0 = *(const float4*)(s_red[w] + 4*tid);
        float4 x1 = *(const float4*)(s_red[w] + DD + 4*tid);
        float4 xa = *(const float4*)(s_red[w] + 2*DD + 4*tid);
        a0[0]+=x0.x; a0[1]+=x0.y; a0[2]+=x0.z; a0[3]+=x0.w;
        a1[0]+=x1.x; a1[1]+=x1.y; a1[2]+=x1.z; a1[3]+=x1.w;
        av[0]=fmaf(xa.x,coef[w],av[0]); av[1]=fmaf(xa.y,coef[w],av[1]);
        av[2]=fmaf(xa.z,coef[w],av[2]); av[3]=fmaf(xa.w,coef[w],av[3]);
    }

    // content-attention logits
    float4 c0v = *(const float4*)(s_c0 + 4*tid);
    float4 c1v = *(const float4*)(s_c1 + 4*tid);
    float4 wca = *(const float4*)(s_Wca + 4*tid);
    float cl0 = tanh_ap(c0v.x + a0[0]) * wca.x + tanh_ap(c0v.y + a0[1]) * wca.y
              + tanh_ap(c0v.z + a0[2]) * wca.z + tanh_ap(c0v.w + a0[3]) * wca.w;
    float cl1 = tanh_ap(c1v.x + a1[0]) * wca.x + tanh_ap(c1v.y + a1[1]) * wca.y
              + tanh_ap(c1v.z + a1[2]) * wca.z + tanh_ap(c1v.w + a1[3]) * wca.w;
#pragma unroll
    for (int o = 16; o; o >>= 1) {
        cl0 += __shfl_xor_sync(0xffffffffu, cl0, o);
        cl1 += __shfl_xor_sync(0xffffffffu, cl1, o);
    }
    if (lane == 0) { s_scalar[warp] = cl0; s_scalar[4 + warp] = cl1; }
    __syncthreads();
    cl0 = s_scalar[0] + s_scalar[1] + s_scalar[2] + s_scalar[3];
    cl1 = s_scalar[4] + s_scalar[5] + s_scalar[6] + s_scalar[7];

    float mx = fmaxf(cl0, cl1);
    float e0 = __expf(cl0 - mx), e1 = __expf(cl1 - mx);
    float einv = 1.f / (e0 + e1);
    float wc0 = e0 * einv, wc1 = e1 * einv;

    // outputs
    float4 o1;
    o1.x = fmaf(c0v.x, wc0, c1v.x * wc1);
    o1.y = fmaf(c0v.y, wc0, c1v.y * wc1);
    o1.z = fmaf(c0v.z, wc0, c1v.z * wc1);
    o1.w = fmaf(c0v.w, wc0, c1v.w * wc1);
    *(float4*)(out + (size_t)b * DD + 4*tid) = o1;

    float4 o2 = make_float4(av[0]*invZ, av[1]*invZ, av[2]*invZ, av[3]*invZ);
    *(float4*)(out + (size_t)BB * DD + (size_t)b * DD + 4*tid) = o2;

    if (tid == 0) {
        out[(size_t)2 * BB * DD + (size_t)b * 2 + 0] = wc0;
        out[(size_t)2 * BB * DD + (size_t)b * 2 + 1] = wc1;
    }
}

extern "C" void kernel_launch(void* const* d_in, const int* in_sizes, int n_in,
                              void* d_out, int out_size)
{
    (void)in_sizes; (void)n_in; (void)out_size;
    const float* text        = (const float*)d_in[0];
    const float* img         = (const float*)d_in[1];
    const float* comment     = (const float*)d_in[2];
    const int*   comment_num = (const int*)d_in[3];
    const float* cow         = (const float*)d_in[4];
    const float* W_ca        = (const float*)d_in[5];
    const float* W_co        = (const float*)d_in[7];
    float* out = (float*)d_out;

    dim3 gg(DD / 64, BB / 64, 2);
    cw_gemm<<<gg, 128>>>(text, img, cow);
    fused_coattn<<<BB, 128>>>(text, img, comment, comment_num, W_ca, W_co, out);
}